// round 11
// baseline (speedup 1.0000x reference)
#include <cuda_runtime.h>
#include <math.h>

#define HID 8
#define KSIZE 5
#define KK (KSIZE * KSIZE * KSIZE)   // 125
#define WSTRIDE 12                   // floats per cell (48B): 16B-aligned halves, spread banks

#define MAX_NODES 50000
__device__ __align__(16) float g_h[MAX_NODES * HID];

__device__ __forceinline__ void red_add_v4(float* addr, float4 v) {
    asm volatile("red.global.add.v4.f32 [%0], {%1,%2,%3,%4};"
                 :: "l"(addr), "f"(v.x), "f"(v.y), "f"(v.z), "f"(v.w) : "memory");
}
__device__ __forceinline__ void red_add_f32(float* addr, float v) {
    asm volatile("red.global.add.f32 [%0], %1;" :: "l"(addr), "f"(v) : "memory");
}

// Blackwell packed f32x2 helpers (FFMA2 is PTX-only; ptxas never auto-fuses)
__device__ __forceinline__ unsigned long long pack2(float lo, float hi) {
    unsigned long long r;
    asm("mov.b64 %0, {%1, %2};" : "=l"(r) : "f"(lo), "f"(hi));
    return r;
}
__device__ __forceinline__ void fma2(unsigned long long& d, unsigned long long a,
                                     unsigned long long b, unsigned long long c) {
    asm("fma.rn.f32x2 %0, %1, %2, %3;" : "=l"(d) : "l"(a), "l"(b), "l"(c));
}
__device__ __forceinline__ float2 unpack2(unsigned long long v) {
    float2 f;
    asm("mov.b64 {%0, %1}, %2;" : "=f"(f.x), "=f"(f.y) : "l"(v));
    return f;
}

__device__ __forceinline__ float elu1(float v) {
    return v > 0.f ? v : expm1f(v);
}

struct Basis {
    int base;
    float w[8];
};

__device__ __forceinline__ Basis make_basis(float p0, float p1, float p2) {
    float pos0 = p0 * (KSIZE - 1), pos1 = p1 * (KSIZE - 1), pos2 = p2 * (KSIZE - 1);
    float f0 = fminf(fmaxf(floorf(pos0), 0.f), (float)(KSIZE - 2));
    float f1 = fminf(fmaxf(floorf(pos1), 0.f), (float)(KSIZE - 2));
    float f2 = fminf(fmaxf(floorf(pos2), 0.f), (float)(KSIZE - 2));
    float r0 = pos0 - f0, r1 = pos1 - f1, r2 = pos2 - f2;
    float u0 = 1.f - r0, u1 = 1.f - r1, u2 = 1.f - r2;
    Basis b;
    b.base = (int)f0 + KSIZE * (int)f1 + KSIZE * KSIZE * (int)f2;
    b.w[0] = u0 * u1 * u2;
    b.w[1] = r0 * u1 * u2;
    b.w[2] = u0 * r1 * u2;
    b.w[3] = r0 * r1 * u2;
    b.w[4] = u0 * u1 * r2;
    b.w[5] = r0 * u1 * r2;
    b.w[6] = u0 * r1 * r2;
    b.w[7] = r0 * r1 * r2;
    return b;
}

__constant__ int c_offs[8] = {0, 1, KSIZE, KSIZE + 1,
                              KSIZE * KSIZE, KSIZE * KSIZE + 1,
                              KSIZE * KSIZE + KSIZE, KSIZE * KSIZE + KSIZE + 1};

// Half-combine: lane's 4 channels (half in {0,1}) of sum_b w_b * W[cell_b][:]
// One LDS.128 + two packed FFMA2 per corner; no converts, fp32 exact.
__device__ __forceinline__ float4 combine_half(const float* sW, const Basis& bs, int half) {
    unsigned long long acc01 = pack2(0.f, 0.f);
    unsigned long long acc23 = pack2(0.f, 0.f);
    const float* sWh = sW + half * 4;
#pragma unroll
    for (int b = 0; b < 8; b++) {
        float4 w = *(const float4*)&sWh[(bs.base + c_offs[b]) * WSTRIDE];
        unsigned long long wb2 = pack2(bs.w[b], bs.w[b]);
        fma2(acc01, wb2, pack2(w.x, w.y), acc01);
        fma2(acc23, wb2, pack2(w.z, w.w), acc23);
    }
    float2 a01 = unpack2(acc01);
    float2 a23 = unpack2(acc23);
    return make_float4(a01.x, a01.y, a23.x, a23.y);
}

__device__ __forceinline__ void load_smem_w(float* sW, const float* W) {
    for (int i = threadIdx.x; i < KK * WSTRIDE; i += blockDim.x) {
        int cell = i / WSTRIDE, o = i - cell * WSTRIDE;
        sW[i] = (o < HID) ? W[cell * HID + o] : 0.f;
    }
    __syncthreads();
}

// K1: h_pre[n][o] = x[n] * root1[o] + bias1[o]
__global__ void k_init_h(const float* __restrict__ x,
                         const float* __restrict__ root1,
                         const float* __restrict__ bias1, int n_nodes) {
    int n = blockIdx.x * blockDim.x + threadIdx.x;
    if (n >= n_nodes) return;
    float xv = x[n];
    float4 r0 = *(const float4*)&root1[0];
    float4 r1 = *(const float4*)&root1[4];
    float4 b0 = *(const float4*)&bias1[0];
    float4 b1 = *(const float4*)&bias1[4];
    float4* hp = (float4*)&g_h[n * HID];
    hp[0] = make_float4(xv * r0.x + b0.x, xv * r0.y + b0.y, xv * r0.z + b0.z, xv * r0.w + b0.w);
    hp[1] = make_float4(xv * r1.x + b1.x, xv * r1.y + b1.y, xv * r1.z + b1.z, xv * r1.w + b1.w);
}

// K2: layer-1, pair-cooperative, 4 edges per pair. lane half=t&1 owns channels [half*4, half*4+4).
__global__ void __launch_bounds__(256, 5)
k_edge1(const int* __restrict__ ei,
        const float* __restrict__ pseudo,
        const float* __restrict__ x,
        const float* __restrict__ W1, int n_edges) {
    __shared__ __align__(16) float sW[KK * WSTRIDE];
    load_smem_w(sW, W1);

    int t = blockIdx.x * blockDim.x + threadIdx.x;
    int p = t >> 1, half = t & 1;
    int e0 = p * 4;
    if (e0 >= n_edges) return;

    int s[4], d[4];
    float pf[12];
    if (e0 + 4 <= n_edges) {
        int4 s4 = *(const int4*)&ei[e0];
        int4 d4 = *(const int4*)&ei[n_edges + e0];
        s[0] = s4.x; s[1] = s4.y; s[2] = s4.z; s[3] = s4.w;
        d[0] = d4.x; d[1] = d4.y; d[2] = d4.z; d[3] = d4.w;
        const float4* pp = (const float4*)&pseudo[3 * e0];
        float4 P0 = pp[0], P1 = pp[1], P2 = pp[2];
        pf[0]=P0.x; pf[1]=P0.y; pf[2]=P0.z; pf[3]=P0.w;
        pf[4]=P1.x; pf[5]=P1.y; pf[6]=P1.z; pf[7]=P1.w;
        pf[8]=P2.x; pf[9]=P2.y; pf[10]=P2.z; pf[11]=P2.w;
    } else {
        for (int k = 0; k < 4; k++) {
            int e = e0 + k;
            bool v = e < n_edges;
            s[k] = v ? ei[e] : 0;
            d[k] = v ? ei[n_edges + e] : 0;
            pf[3*k]   = v ? pseudo[3*e]   : 0.f;
            pf[3*k+1] = v ? pseudo[3*e+1] : 0.f;
            pf[3*k+2] = v ? pseudo[3*e+2] : 0.f;
        }
    }

    float xj[4];
#pragma unroll
    for (int k = 0; k < 4; k++) xj[k] = __ldg(&x[s[k]]);

    float4 a[4];
#pragma unroll
    for (int k = 0; k < 4; k++) {
        Basis bs = make_basis(pf[3*k], pf[3*k+1], pf[3*k+2]);
        a[k] = combine_half(sW, bs, half);
    }
#pragma unroll
    for (int k = 0; k < 4; k++) {
        if (e0 + k < n_edges)
            red_add_v4(&g_h[d[k] * HID + half * 4],
                       make_float4(xj[k] * a[k].x, xj[k] * a[k].y,
                                   xj[k] * a[k].z, xj[k] * a[k].w));
    }
}

// K3: h = elu(h_pre) in place; out_pre[n] = h . root2 + bias2
__global__ void k_act1(const float* __restrict__ root2,
                       const float* __restrict__ bias2,
                       float* __restrict__ out, int n_nodes) {
    int n = blockIdx.x * blockDim.x + threadIdx.x;
    if (n >= n_nodes) return;
    float4* hp = (float4*)&g_h[n * HID];
    float4 h0 = hp[0], h1 = hp[1];
    h0.x = elu1(h0.x); h0.y = elu1(h0.y); h0.z = elu1(h0.z); h0.w = elu1(h0.w);
    h1.x = elu1(h1.x); h1.y = elu1(h1.y); h1.z = elu1(h1.z); h1.w = elu1(h1.w);
    hp[0] = h0; hp[1] = h1;
    float4 r0 = *(const float4*)&root2[0];
    float4 r1 = *(const float4*)&root2[4];
    float acc = bias2[0]
              + h0.x * r0.x + h0.y * r0.y + h0.z * r0.z + h0.w * r0.w
              + h1.x * r1.x + h1.y * r1.y + h1.z * r1.z + h1.w * r1.w;
    out[n] = acc;
}

// K4: layer-2, pair-cooperative, 4 edges per pair; front-batched 16B gathers.
__global__ void __launch_bounds__(256, 5)
k_edge2(const int* __restrict__ ei,
        const float* __restrict__ pseudo,
        const float* __restrict__ W2,
        float* __restrict__ out, int n_edges) {
    __shared__ __align__(16) float sW[KK * WSTRIDE];
    load_smem_w(sW, W2);

    int t = blockIdx.x * blockDim.x + threadIdx.x;
    int p = t >> 1, half = t & 1;
    int e0 = p * 4;
    if (e0 >= n_edges) return;

    int s[4], d[4];
    float pf[12];
    if (e0 + 4 <= n_edges) {
        int4 s4 = *(const int4*)&ei[e0];
        int4 d4 = *(const int4*)&ei[n_edges + e0];
        s[0] = s4.x; s[1] = s4.y; s[2] = s4.z; s[3] = s4.w;
        d[0] = d4.x; d[1] = d4.y; d[2] = d4.z; d[3] = d4.w;
        const float4* pp = (const float4*)&pseudo[3 * e0];
        float4 P0 = pp[0], P1 = pp[1], P2 = pp[2];
        pf[0]=P0.x; pf[1]=P0.y; pf[2]=P0.z; pf[3]=P0.w;
        pf[4]=P1.x; pf[5]=P1.y; pf[6]=P1.z; pf[7]=P1.w;
        pf[8]=P2.x; pf[9]=P2.y; pf[10]=P2.z; pf[11]=P2.w;
    } else {
        for (int k = 0; k < 4; k++) {
            int e = e0 + k;
            bool v = e < n_edges;
            s[k] = v ? ei[e] : 0;
            d[k] = v ? ei[n_edges + e] : 0;
            pf[3*k]   = v ? pseudo[3*e]   : 0.f;
            pf[3*k+1] = v ? pseudo[3*e+1] : 0.f;
            pf[3*k+2] = v ? pseudo[3*e+2] : 0.f;
        }
    }

    // front-batched scattered 16B gathers (this lane's half of h[src])
    float4 hh[4];
#pragma unroll
    for (int k = 0; k < 4; k++)
        hh[k] = *(const float4*)&g_h[s[k] * HID + half * 4];

    float v[4];
#pragma unroll
    for (int k = 0; k < 4; k++) {
        Basis bs = make_basis(pf[3*k], pf[3*k+1], pf[3*k+2]);
        float4 a = combine_half(sW, bs, half);
        v[k] = a.x * hh[k].x + a.y * hh[k].y + a.z * hh[k].z + a.w * hh[k].w;
    }

    unsigned mask = __activemask();
#pragma unroll
    for (int k = 0; k < 4; k++)
        v[k] += __shfl_xor_sync(mask, v[k], 1);

    if (half == 0) {
#pragma unroll
        for (int k = 0; k < 4; k++)
            if (e0 + k < n_edges) red_add_f32(&out[d[k]], v[k]);
    }
}

// K5: out = elu(out) in place
__global__ void k_act2(float* __restrict__ out, int n_nodes) {
    int n = blockIdx.x * blockDim.x + threadIdx.x;
    if (n < n_nodes) out[n] = elu1(out[n]);
}

extern "C" void kernel_launch(void* const* d_in, const int* in_sizes, int n_in,
                              void* d_out, int out_size) {
    const float* x      = (const float*)d_in[0];
    const int*   ei     = (const int*)d_in[1];      // int32 (JAX x64 disabled)
    const float* pseudo = (const float*)d_in[2];
    const float* W1     = (const float*)d_in[3];
    const float* root1  = (const float*)d_in[4];
    const float* bias1  = (const float*)d_in[5];
    const float* W2     = (const float*)d_in[6];
    const float* root2  = (const float*)d_in[7];
    const float* bias2  = (const float*)d_in[8];
    float* out = (float*)d_out;

    int n_nodes = in_sizes[0];
    int n_edges = in_sizes[1] / 2;

    const int T = 256;
    int n_pairs = (n_edges + 3) / 4;
    int eb = (2 * n_pairs + T - 1) / T;
    k_init_h<<<(n_nodes + T - 1) / T, T>>>(x, root1, bias1, n_nodes);
    k_edge1<<<eb, T>>>(ei, pseudo, x, W1, n_edges);
    k_act1<<<(n_nodes + T - 1) / T, T>>>(root2, bias2, out, n_nodes);
    k_edge2<<<eb, T>>>(ei, pseudo, W2, out, n_edges);
    k_act2<<<(n_nodes + T - 1) / T, T>>>(out, n_nodes);
}

// round 12
// speedup vs baseline: 1.3309x; 1.3309x over previous
#include <cuda_runtime.h>
#include <cuda_fp16.h>
#include <math.h>

#define HID 8
#define KSIZE 5
#define KK (KSIZE * KSIZE * KSIZE)   // 125
#define HSTRIDE 20                   // halfs per cell (40B): 8B-aligned half-rows, spread banks

#define MAX_NODES 50000
__device__ __align__(16) float g_h[MAX_NODES * HID];

__device__ __forceinline__ void red_add_v4(float* addr, float4 v) {
    asm volatile("red.global.add.v4.f32 [%0], {%1,%2,%3,%4};"
                 :: "l"(addr), "f"(v.x), "f"(v.y), "f"(v.z), "f"(v.w) : "memory");
}
__device__ __forceinline__ void red_add_f32(float* addr, float v) {
    asm volatile("red.global.add.f32 [%0], %1;" :: "l"(addr), "f"(v) : "memory");
}

__device__ __forceinline__ float elu1(float v) {
    return v > 0.f ? v : expm1f(v);
}

struct Basis {
    int base;
    float w[8];
};

__device__ __forceinline__ Basis make_basis(float p0, float p1, float p2) {
    float pos0 = p0 * (KSIZE - 1), pos1 = p1 * (KSIZE - 1), pos2 = p2 * (KSIZE - 1);
    float f0 = fminf(fmaxf(floorf(pos0), 0.f), (float)(KSIZE - 2));
    float f1 = fminf(fmaxf(floorf(pos1), 0.f), (float)(KSIZE - 2));
    float f2 = fminf(fmaxf(floorf(pos2), 0.f), (float)(KSIZE - 2));
    float r0 = pos0 - f0, r1 = pos1 - f1, r2 = pos2 - f2;
    float u0 = 1.f - r0, u1 = 1.f - r1, u2 = 1.f - r2;
    Basis b;
    b.base = (int)f0 + KSIZE * (int)f1 + KSIZE * KSIZE * (int)f2;
    b.w[0] = u0 * u1 * u2;
    b.w[1] = r0 * u1 * u2;
    b.w[2] = u0 * r1 * u2;
    b.w[3] = r0 * r1 * u2;
    b.w[4] = u0 * u1 * r2;
    b.w[5] = r0 * u1 * r2;
    b.w[6] = u0 * r1 * r2;
    b.w[7] = r0 * r1 * r2;
    return b;
}

__constant__ int c_offs[8] = {0, 1, KSIZE, KSIZE + 1,
                              KSIZE * KSIZE, KSIZE * KSIZE + 1,
                              KSIZE * KSIZE + KSIZE, KSIZE * KSIZE + KSIZE + 1};

// Half-combine from fp16 table: lane's 4 channels (half in {0,1}) of sum_b w_b * W[cell_b][:]
// One 8B LDS.64 per corner.
__device__ __forceinline__ float4 combine_half(const __half* sH, const Basis& bs, int half) {
    float4 a = make_float4(0.f, 0.f, 0.f, 0.f);
    const __half* sHh = sH + half * 4;
#pragma unroll
    for (int b = 0; b < 8; b++) {
        __half2 raw2[2];
        *(uint2*)raw2 = *(const uint2*)&sHh[(bs.base + c_offs[b]) * HSTRIDE];
        float2 f01 = __half22float2(raw2[0]);
        float2 f23 = __half22float2(raw2[1]);
        float wb = bs.w[b];
        a.x += wb * f01.x; a.y += wb * f01.y;
        a.z += wb * f23.x; a.w += wb * f23.y;
    }
    return a;
}

__device__ __forceinline__ void load_smem_w(__half* sH, const float* W) {
    for (int i = threadIdx.x; i < KK * HSTRIDE; i += blockDim.x) {
        int cell = i / HSTRIDE, o = i - cell * HSTRIDE;
        sH[i] = __float2half((o < HID) ? W[cell * HID + o] : 0.f);
    }
    __syncthreads();
}

// K1: h_pre[n][o] = x[n] * root1[o] + bias1[o]
__global__ void k_init_h(const float* __restrict__ x,
                         const float* __restrict__ root1,
                         const float* __restrict__ bias1, int n_nodes) {
    int n = blockIdx.x * blockDim.x + threadIdx.x;
    if (n >= n_nodes) return;
    float xv = x[n];
    float4 r0 = *(const float4*)&root1[0];
    float4 r1 = *(const float4*)&root1[4];
    float4 b0 = *(const float4*)&bias1[0];
    float4 b1 = *(const float4*)&bias1[4];
    float4* hp = (float4*)&g_h[n * HID];
    hp[0] = make_float4(xv * r0.x + b0.x, xv * r0.y + b0.y, xv * r0.z + b0.z, xv * r0.w + b0.w);
    hp[1] = make_float4(xv * r1.x + b1.x, xv * r1.y + b1.y, xv * r1.z + b1.z, xv * r1.w + b1.w);
}

// K2: layer-1, pair-cooperative, 4 edges per pair. lane half=t&1 owns channels [half*4, half*4+4).
__global__ void __launch_bounds__(256, 6)
k_edge1(const int* __restrict__ ei,
        const float* __restrict__ pseudo,
        const float* __restrict__ x,
        const float* __restrict__ W1, int n_edges) {
    __shared__ __align__(16) __half sH[KK * HSTRIDE];
    load_smem_w(sH, W1);

    int t = blockIdx.x * blockDim.x + threadIdx.x;
    int p = t >> 1, half = t & 1;
    int e0 = p * 4;
    if (e0 >= n_edges) return;

    int s[4], d[4];
    float pf[12];
    if (e0 + 4 <= n_edges) {
        int4 s4 = *(const int4*)&ei[e0];
        int4 d4 = *(const int4*)&ei[n_edges + e0];
        s[0] = s4.x; s[1] = s4.y; s[2] = s4.z; s[3] = s4.w;
        d[0] = d4.x; d[1] = d4.y; d[2] = d4.z; d[3] = d4.w;
        const float4* pp = (const float4*)&pseudo[3 * e0];
        float4 P0 = pp[0], P1 = pp[1], P2 = pp[2];
        pf[0]=P0.x; pf[1]=P0.y; pf[2]=P0.z; pf[3]=P0.w;
        pf[4]=P1.x; pf[5]=P1.y; pf[6]=P1.z; pf[7]=P1.w;
        pf[8]=P2.x; pf[9]=P2.y; pf[10]=P2.z; pf[11]=P2.w;
    } else {
        for (int k = 0; k < 4; k++) {
            int e = e0 + k;
            bool v = e < n_edges;
            s[k] = v ? ei[e] : 0;
            d[k] = v ? ei[n_edges + e] : 0;
            pf[3*k]   = v ? pseudo[3*e]   : 0.f;
            pf[3*k+1] = v ? pseudo[3*e+1] : 0.f;
            pf[3*k+2] = v ? pseudo[3*e+2] : 0.f;
        }
    }

    float xj[4];
#pragma unroll
    for (int k = 0; k < 4; k++) xj[k] = __ldg(&x[s[k]]);

    float4 a[4];
#pragma unroll
    for (int k = 0; k < 4; k++) {
        Basis bs = make_basis(pf[3*k], pf[3*k+1], pf[3*k+2]);
        a[k] = combine_half(sH, bs, half);
    }
#pragma unroll
    for (int k = 0; k < 4; k++) {
        if (e0 + k < n_edges)
            red_add_v4(&g_h[d[k] * HID + half * 4],
                       make_float4(xj[k] * a[k].x, xj[k] * a[k].y,
                                   xj[k] * a[k].z, xj[k] * a[k].w));
    }
}

// K3: h = elu(h_pre) in place; out_pre[n] = h . root2 + bias2
__global__ void k_act1(const float* __restrict__ root2,
                       const float* __restrict__ bias2,
                       float* __restrict__ out, int n_nodes) {
    int n = blockIdx.x * blockDim.x + threadIdx.x;
    if (n >= n_nodes) return;
    float4* hp = (float4*)&g_h[n * HID];
    float4 h0 = hp[0], h1 = hp[1];
    h0.x = elu1(h0.x); h0.y = elu1(h0.y); h0.z = elu1(h0.z); h0.w = elu1(h0.w);
    h1.x = elu1(h1.x); h1.y = elu1(h1.y); h1.z = elu1(h1.z); h1.w = elu1(h1.w);
    hp[0] = h0; hp[1] = h1;
    float4 r0 = *(const float4*)&root2[0];
    float4 r1 = *(const float4*)&root2[4];
    float acc = bias2[0]
              + h0.x * r0.x + h0.y * r0.y + h0.z * r0.z + h0.w * r0.w
              + h1.x * r1.x + h1.y * r1.y + h1.z * r1.z + h1.w * r1.w;
    out[n] = acc;
}

// K4: layer-2, pair-cooperative, 4 edges per pair; front-batched 16B gathers.
__global__ void __launch_bounds__(256, 6)
k_edge2(const int* __restrict__ ei,
        const float* __restrict__ pseudo,
        const float* __restrict__ W2,
        float* __restrict__ out, int n_edges) {
    __shared__ __align__(16) __half sH[KK * HSTRIDE];
    load_smem_w(sH, W2);

    int t = blockIdx.x * blockDim.x + threadIdx.x;
    int p = t >> 1, half = t & 1;
    int e0 = p * 4;
    if (e0 >= n_edges) return;

    int s[4], d[4];
    float pf[12];
    if (e0 + 4 <= n_edges) {
        int4 s4 = *(const int4*)&ei[e0];
        int4 d4 = *(const int4*)&ei[n_edges + e0];
        s[0] = s4.x; s[1] = s4.y; s[2] = s4.z; s[3] = s4.w;
        d[0] = d4.x; d[1] = d4.y; d[2] = d4.z; d[3] = d4.w;
        const float4* pp = (const float4*)&pseudo[3 * e0];
        float4 P0 = pp[0], P1 = pp[1], P2 = pp[2];
        pf[0]=P0.x; pf[1]=P0.y; pf[2]=P0.z; pf[3]=P0.w;
        pf[4]=P1.x; pf[5]=P1.y; pf[6]=P1.z; pf[7]=P1.w;
        pf[8]=P2.x; pf[9]=P2.y; pf[10]=P2.z; pf[11]=P2.w;
    } else {
        for (int k = 0; k < 4; k++) {
            int e = e0 + k;
            bool v = e < n_edges;
            s[k] = v ? ei[e] : 0;
            d[k] = v ? ei[n_edges + e] : 0;
            pf[3*k]   = v ? pseudo[3*e]   : 0.f;
            pf[3*k+1] = v ? pseudo[3*e+1] : 0.f;
            pf[3*k+2] = v ? pseudo[3*e+2] : 0.f;
        }
    }

    // front-batched scattered 16B gathers (this lane's half of h[src])
    float4 hh[4];
#pragma unroll
    for (int k = 0; k < 4; k++)
        hh[k] = *(const float4*)&g_h[s[k] * HID + half * 4];

    float v[4];
#pragma unroll
    for (int k = 0; k < 4; k++) {
        Basis bs = make_basis(pf[3*k], pf[3*k+1], pf[3*k+2]);
        float4 a = combine_half(sH, bs, half);
        v[k] = a.x * hh[k].x + a.y * hh[k].y + a.z * hh[k].z + a.w * hh[k].w;
    }

    unsigned mask = __activemask();
#pragma unroll
    for (int k = 0; k < 4; k++)
        v[k] += __shfl_xor_sync(mask, v[k], 1);

    if (half == 0) {
#pragma unroll
        for (int k = 0; k < 4; k++)
            if (e0 + k < n_edges) red_add_f32(&out[d[k]], v[k]);
    }
}

// K5: out = elu(out) in place
__global__ void k_act2(float* __restrict__ out, int n_nodes) {
    int n = blockIdx.x * blockDim.x + threadIdx.x;
    if (n < n_nodes) out[n] = elu1(out[n]);
}

extern "C" void kernel_launch(void* const* d_in, const int* in_sizes, int n_in,
                              void* d_out, int out_size) {
    const float* x      = (const float*)d_in[0];
    const int*   ei     = (const int*)d_in[1];      // int32 (JAX x64 disabled)
    const float* pseudo = (const float*)d_in[2];
    const float* W1     = (const float*)d_in[3];
    const float* root1  = (const float*)d_in[4];
    const float* bias1  = (const float*)d_in[5];
    const float* W2     = (const float*)d_in[6];
    const float* root2  = (const float*)d_in[7];
    const float* bias2  = (const float*)d_in[8];
    float* out = (float*)d_out;

    int n_nodes = in_sizes[0];
    int n_edges = in_sizes[1] / 2;

    const int T = 256;
    int n_pairs = (n_edges + 3) / 4;
    int eb = (2 * n_pairs + T - 1) / T;
    k_init_h<<<(n_nodes + T - 1) / T, T>>>(x, root1, bias1, n_nodes);
    k_edge1<<<eb, T>>>(ei, pseudo, x, W1, n_edges);
    k_act1<<<(n_nodes + T - 1) / T, T>>>(root2, bias2, out, n_nodes);
    k_edge2<<<eb, T>>>(ei, pseudo, W2, out, n_edges);
    k_act2<<<(n_nodes + T - 1) / T, T>>>(out, n_nodes);
}